// round 2
// baseline (speedup 1.0000x reference)
#include <cuda_runtime.h>
#include <math.h>

#define KDIM 512
#define CDIM 896
#define HDIM 448
#define GDIM 1792   // 4*H
#define BDIM 8
#define EDIM 4
#define ALPHA_F 5e-4f
#define EPS_F 1e-6f
#define OBS_STD_F 0.1f

static const long MEAN_N = (long)BDIM * KDIM * CDIM;   // 3670016
static const long COV_N  = (long)BDIM * KDIM * KDIM;   // 2097152

// ---------------- scratch (no allocations allowed) ----------------
__device__ float g_Pa[BDIM * CDIM * KDIM];
__device__ float g_Pb[BDIM * CDIM * KDIM];
__device__ float g_Mm[BDIM * CDIM * CDIM];
__device__ float g_xin0[BDIM * EDIM * CDIM];
__device__ float g_xin1[BDIM * EDIM * CDIM];
__device__ float g_zl[EDIM * BDIM * CDIM];
__device__ float g_hseq[2 * BDIM * EDIM * HDIM];
__device__ float g_gates[2 * BDIM * GDIM];
__device__ float g_hst[2 * BDIM * HDIM];
__device__ float g_cst[2 * BDIM * HDIM];
__device__ float g_w[BDIM * KDIM];
__device__ float g_wU[BDIM * KDIM];
__device__ float g_cv[BDIM * KDIM];
__device__ float g_Dc[BDIM * CDIM];
__device__ float g_part[BDIM];

__device__ __forceinline__ float sigf(float x) { return 1.0f / (1.0f + expf(-x)); }
__device__ __forceinline__ float clipf(float x, float lo, float hi) {
    return fminf(fmaxf(x, lo), hi);
}

// ---------------- init ----------------
__global__ void init_mean_kernel(float* mean, const float* mm) {
    long i = (long)blockIdx.x * blockDim.x + threadIdx.x;
    if (i < MEAN_N) mean[i] = mm[i % ((long)KDIM * CDIM)];
}
__global__ void init_cov_kernel(float* cov) {
    long i = (long)blockIdx.x * blockDim.x + threadIdx.x;
    if (i < COV_N) {
        int j = (int)(i % KDIM);
        int k = (int)((i / KDIM) % KDIM);
        cov[i] = (j == k) ? (1.0f + EPS_F) : 0.0f;
    }
}
__global__ void zero_kernel(float* p, int n) {
    int i = blockIdx.x * blockDim.x + threadIdx.x;
    if (i < n) p[i] = 0.0f;
}

// ---------------- LSTM ----------------
__global__ void build_xin0_kernel(float* xin, const float* z) {
    int i = blockIdx.x * blockDim.x + threadIdx.x;
    int n = BDIM * EDIM * CDIM;
    if (i < n) {
        int c = i % CDIM;
        int t = (i / CDIM) % EDIM;
        int b = i / (CDIM * EDIM);
        xin[i] = z[((long)t * BDIM + b) * CDIM + c];
    }
}

// one warp per (d,b,j) gate; dot over C (input) + H (hidden)
__global__ void lstm_gates_kernel(const float* __restrict__ xin,
                                  const float* __restrict__ hcur,
                                  const float* __restrict__ Wih,
                                  const float* __restrict__ Whh,
                                  const float* __restrict__ bias,
                                  float* __restrict__ gates, int step) {
    int w = (blockIdx.x * blockDim.x + threadIdx.x) >> 5;
    int lane = threadIdx.x & 31;
    if (w >= 2 * BDIM * GDIM) return;
    int j = w % GDIM;
    int b = (w / GDIM) % BDIM;
    int d = w / (GDIM * BDIM);
    int t = (d == 0) ? step : (EDIM - 1 - step);

    const float* x  = xin + ((long)b * EDIM + t) * CDIM;
    const float* wi = Wih + ((long)d * GDIM + j) * CDIM;
    float acc = 0.0f;
#pragma unroll
    for (int c = lane * 4; c < CDIM; c += 128) {
        float4 xv = *(const float4*)(x + c);
        float4 wv = *(const float4*)(wi + c);
        acc += xv.x * wv.x + xv.y * wv.y + xv.z * wv.z + xv.w * wv.w;
    }
    const float* h  = hcur + ((long)d * BDIM + b) * HDIM;
    const float* wh = Whh + ((long)d * GDIM + j) * HDIM;
    for (int c = lane * 4; c < HDIM; c += 128) {
        float4 hv = *(const float4*)(h + c);
        float4 wv = *(const float4*)(wh + c);
        acc += hv.x * wv.x + hv.y * wv.y + hv.z * wv.z + hv.w * wv.w;
    }
#pragma unroll
    for (int o = 16; o > 0; o >>= 1) acc += __shfl_xor_sync(0xffffffffu, acc, o);
    if (lane == 0) gates[((long)d * BDIM + b) * GDIM + j] = acc + bias[(long)d * GDIM + j];
}

__global__ void lstm_update_kernel(const float* __restrict__ gates,
                                   float* __restrict__ hcur, float* __restrict__ ccur,
                                   float* __restrict__ hseq, int step) {
    int i = blockIdx.x * blockDim.x + threadIdx.x;
    int n = 2 * BDIM * HDIM;
    if (i >= n) return;
    int h = i % HDIM;
    int b = (i / HDIM) % BDIM;
    int d = i / (HDIM * BDIM);
    int t = (d == 0) ? step : (EDIM - 1 - step);
    const float* g = gates + ((long)d * BDIM + b) * GDIM;
    float gi = g[h], gf = g[HDIM + h], gg = g[2 * HDIM + h], go = g[3 * HDIM + h];
    float c = ccur[i];
    c = sigf(gf) * c + sigf(gi) * tanhf(gg);
    float hh = sigf(go) * tanhf(c);
    ccur[i] = c;
    hcur[i] = hh;
    hseq[(((long)d * BDIM + b) * EDIM + t) * HDIM + h] = hh;
}

// concat fwd/bwd hidden into (B,T,C) layer input
__global__ void concat_kernel(const float* __restrict__ hseq, float* __restrict__ xout) {
    int i = blockIdx.x * blockDim.x + threadIdx.x;
    int n = BDIM * EDIM * CDIM;
    if (i >= n) return;
    int c = i % CDIM;
    int t = (i / CDIM) % EDIM;
    int b = i / (CDIM * EDIM);
    int d = (c >= HDIM) ? 1 : 0;
    int hh = c - d * HDIM;
    xout[i] = hseq[(((long)d * BDIM + b) * EDIM + t) * HDIM + hh];
}
// build zl (E,B,C) from layer-1 hseq
__global__ void build_zl_kernel(const float* __restrict__ hseq, float* __restrict__ zl) {
    int i = blockIdx.x * blockDim.x + threadIdx.x;
    int n = EDIM * BDIM * CDIM;
    if (i >= n) return;
    int c = i % CDIM;
    int b = (i / CDIM) % BDIM;
    int t = i / (CDIM * BDIM);
    int d = (c >= HDIM) ? 1 : 0;
    int hh = c - d * HDIM;
    zl[i] = hseq[(((long)d * BDIM + b) * EDIM + t) * HDIM + hh];
}

// ---------------- transpose-scale: P = alpha * mean^T ----------------
__global__ void transpose_scale_kernel(const float* __restrict__ mean, float* __restrict__ P) {
    __shared__ float tile[32][33];
    int b = blockIdx.z;
    int k0 = blockIdx.x * 32, c0 = blockIdx.y * 32;
    const float* M = mean + (long)b * KDIM * CDIM;
    float* Pp = P + (long)b * CDIM * KDIM;
    for (int i = threadIdx.y; i < 32; i += 8)
        tile[i][threadIdx.x] = M[(long)(k0 + i) * CDIM + c0 + threadIdx.x];
    __syncthreads();
    for (int i = threadIdx.y; i < 32; i += 8)
        Pp[(long)(c0 + i) * KDIM + k0 + threadIdx.x] = ALPHA_F * tile[threadIdx.x][i];
}

// ---------------- batched SGEMM 128x64x8, 128 threads, 8x8/thread ----------------
template <int EPI>
__global__ __launch_bounds__(128) void sgemm_kernel(
    const float* __restrict__ A, const float* __restrict__ B,
    const float* __restrict__ Ead, float* __restrict__ C,
    int Mdim, int Ndim, int Kd, long sA, long sB, long sC) {
    int bb = blockIdx.z;
    A += (long)bb * sA;
    B += (long)bb * sB;
    C += (long)bb * sC;
    if (EPI) Ead += (long)bb * sC;

    int m0 = blockIdx.y * 128, n0 = blockIdx.x * 64;
    __shared__ float As[8][128];
    __shared__ float Bs[8][64];
    int tid = threadIdx.x;
    int ty = tid >> 3, tx = tid & 7;   // 16 x 8
    float acc[8][8];
#pragma unroll
    for (int i = 0; i < 8; i++)
#pragma unroll
        for (int j = 0; j < 8; j++) acc[i][j] = 0.0f;

    const float* Ag = A + (long)(m0 + tid) * Kd;
    int brow = tid >> 4, bcol = (tid & 15) * 4;
    const float* Bg = B + (long)brow * Ndim + n0 + bcol;

    for (int k0 = 0; k0 < Kd; k0 += 8) {
        float4 a0 = *(const float4*)(Ag + k0);
        float4 a1 = *(const float4*)(Ag + k0 + 4);
        float4 b0 = *(const float4*)(Bg + (long)k0 * Ndim);
        As[0][tid] = a0.x; As[1][tid] = a0.y; As[2][tid] = a0.z; As[3][tid] = a0.w;
        As[4][tid] = a1.x; As[5][tid] = a1.y; As[6][tid] = a1.z; As[7][tid] = a1.w;
        *(float4*)&Bs[brow][bcol] = b0;
        __syncthreads();
#pragma unroll
        for (int kk = 0; kk < 8; kk++) {
            float ar[8], br[8];
            *(float4*)ar = *(float4*)&As[kk][ty * 8];
            *(float4*)(ar + 4) = *(float4*)&As[kk][ty * 8 + 4];
            *(float4*)br = *(float4*)&Bs[kk][tx * 8];
            *(float4*)(br + 4) = *(float4*)&Bs[kk][tx * 8 + 4];
#pragma unroll
            for (int i = 0; i < 8; i++)
#pragma unroll
                for (int j = 0; j < 8; j++) acc[i][j] += ar[i] * br[j];
        }
        __syncthreads();
    }
#pragma unroll
    for (int i = 0; i < 8; i++) {
        long row = m0 + ty * 8 + i;
        float* Cr = C + row * Ndim + n0 + tx * 8;
        if (EPI) {
            const float* Er = Ead + row * Ndim + n0 + tx * 8;
#pragma unroll
            for (int j = 0; j < 8; j += 4) {
                float4 e = *(const float4*)(Er + j);
                float4 v;
                v.x = 2.0f * e.x - acc[i][j];
                v.y = 2.0f * e.y - acc[i][j + 1];
                v.z = 2.0f * e.z - acc[i][j + 2];
                v.w = 2.0f * e.w - acc[i][j + 3];
                *(float4*)(Cr + j) = v;
            }
        } else {
#pragma unroll
            for (int j = 0; j < 8; j += 4) {
                float4 v;
                v.x = acc[i][j]; v.y = acc[i][j + 1]; v.z = acc[i][j + 2]; v.w = acc[i][j + 3];
                *(float4*)(Cr + j) = v;
            }
        }
    }
}

// ---------------- episode update kernels ----------------
__global__ void w_kernel(const float* __restrict__ zl, const float* __restrict__ noise,
                         const float* __restrict__ P, float* __restrict__ wv, int t) {
    int b = blockIdx.x;
    int k = threadIdx.x;  // 512
    __shared__ float zn[CDIM];
    const float* zr = zl + ((long)t * BDIM + b) * CDIM;
    const float* nr = noise + ((long)t * BDIM + b) * CDIM;
    for (int c = k; c < CDIM; c += KDIM) zn[c] = zr[c] + OBS_STD_F * nr[c];
    __syncthreads();
    const float* Pb = P + (long)b * CDIM * KDIM;
    float acc = 0.0f;
    for (int c = 0; c < CDIM; c++) acc += zn[c] * Pb[(long)c * KDIM + k];
    wv[b * KDIM + k] = acc;
}

__global__ void delta_kernel(const float* __restrict__ wv, const float* __restrict__ mean,
                             const float* __restrict__ zl, float* __restrict__ Dc, int t) {
    int b = blockIdx.y;
    int c = blockIdx.x * 128 + threadIdx.x;  // 7 x 128 = 896
    __shared__ float sw[KDIM];
    for (int k = threadIdx.x; k < KDIM; k += 128) sw[k] = wv[b * KDIM + k];
    __syncthreads();
    const float* M = mean + (long)b * KDIM * CDIM;
    float acc = 0.0f;
    for (int k = 0; k < KDIM; k++) acc += sw[k] * M[(long)k * CDIM + c];
    float d = zl[((long)t * BDIM + b) * CDIM + c] - acc;
    Dc[b * CDIM + c] = clipf(d, -100.0f, 100.0f);
}

__global__ void wU_kernel(const float* __restrict__ wv, const float* __restrict__ cov,
                          float* __restrict__ wU) {
    int b = blockIdx.y;
    int j = blockIdx.x * 128 + threadIdx.x;  // 4 x 128 = 512
    __shared__ float sw[KDIM];
    for (int k = threadIdx.x; k < KDIM; k += 128) sw[k] = wv[b * KDIM + k];
    __syncthreads();
    const float* Cb = cov + (long)b * KDIM * KDIM;
    float acc = 0.0f;
    for (int k = 0; k < KDIM; k++) acc += sw[k] * Cb[(long)k * KDIM + j];
    wU[b * KDIM + j] = acc;
}

__global__ void sigma_c_kernel(const float* __restrict__ wv, const float* __restrict__ wU,
                               float* __restrict__ cv) {
    int b = blockIdx.x;
    int k = threadIdx.x;  // 512
    __shared__ float red[KDIM];
    float u = wU[b * KDIM + k];
    red[k] = u * wv[b * KDIM + k];
    __syncthreads();
    for (int s = 256; s > 0; s >>= 1) {
        if (k < s) red[k] += red[k + s];
        __syncthreads();
    }
    float sigma = fmaxf(red[0] + OBS_STD_F * OBS_STD_F, EPS_F);
    cv[b * KDIM + k] = clipf(u / sigma, -1000.0f, 1000.0f);
}

__global__ void mean_update_kernel(float* __restrict__ mean, const float* __restrict__ cv,
                                   const float* __restrict__ Dc) {
    long i = (long)blockIdx.x * blockDim.x + threadIdx.x;
    if (i >= MEAN_N) return;
    int c = (int)(i % CDIM);
    int k = (int)((i / CDIM) % KDIM);
    int b = (int)(i / ((long)CDIM * KDIM));
    float v = mean[i] + cv[b * KDIM + k] * Dc[b * CDIM + c];
    mean[i] = clipf(v, -1000.0f, 1000.0f);
}

__global__ void cov_update_kernel(float* __restrict__ cov, const float* __restrict__ cv,
                                  const float* __restrict__ wU) {
    long i = (long)blockIdx.x * blockDim.x + threadIdx.x;
    if (i >= COV_N) return;
    int j = (int)(i % KDIM);
    int k = (int)((i / KDIM) % KDIM);
    int b = (int)(i / ((long)KDIM * KDIM));
    float ci = cv[b * KDIM + k], cj = cv[b * KDIM + j];
    float ui = wU[b * KDIM + k], uj = wU[b * KDIM + j];
    float old = cov[i];
    float v;
    if (k == j) {
        v = clipf(old - ci * ui, 0.001f, 1000.0f) + EPS_F;
    } else {
        v = old - 0.5f * (ci * uj + cj * ui);
    }
    cov[i] = v;
}

// ---------------- KL ----------------
__global__ void dkl_part_kernel(const float* __restrict__ mean, const float* __restrict__ cov,
                                const float* __restrict__ prior, float* __restrict__ part) {
    int b = blockIdx.x;
    int tid = threadIdx.x;  // 256
    const float pdiag = 1.0f + EPS_F;  // clip(1+eps, 0.001, 1e6)
    float rsum = 0.0f, lsum = 0.0f;
    const float* Cb = cov + (long)b * KDIM * KDIM;
    for (int k = tid; k < KDIM; k += 256) {
        float q = clipf(Cb[(long)k * KDIM + k], 0.001f, 1e6f);
        rsum += clipf(q / pdiag, EPS_F, 1000.0f);
        lsum += clipf(logf(pdiag) - logf(q), -10.0f, 10.0f);
    }
    float t2a = 0.0f, t2b = 0.0f;
    const float* Mb = mean + (long)b * KDIM * CDIM;
    long n = (long)KDIM * CDIM;
    for (long i = tid; i < n; i += 512) {
        float d = Mb[i] - prior[i];
        t2a += fminf(d * d, 1000.0f);
        long i2 = i + 256;
        if (i2 < n) {
            float d2 = Mb[i2] - prior[i2];
            t2b += fminf(d2 * d2, 1000.0f);
        }
    }
    float t2s = t2a + t2b;
    __shared__ double sd[256];
    sd[tid] = (double)rsum;
    __syncthreads();
    for (int s = 128; s > 0; s >>= 1) { if (tid < s) sd[tid] += sd[tid + s]; __syncthreads(); }
    double Rs = sd[0]; __syncthreads();
    sd[tid] = (double)lsum;
    __syncthreads();
    for (int s = 128; s > 0; s >>= 1) { if (tid < s) sd[tid] += sd[tid + s]; __syncthreads(); }
    double Ls = sd[0]; __syncthreads();
    sd[tid] = (double)t2s;
    __syncthreads();
    for (int s = 128; s > 0; s >>= 1) { if (tid < s) sd[tid] += sd[tid + s]; __syncthreads(); }
    double T2s = sd[0];
    if (tid == 0) {
        float t1 = clipf((float)CDIM * (float)Rs, -1e6f, 1e6f);
        float t2 = clipf((float)(T2s) / pdiag, -1e6f, 1e6f);
        float t3 = -(float)CDIM * (float)KDIM;
        float t4 = clipf((float)CDIM * (float)Ls, -1e6f, 1e6f);
        part[b] = t1 + t2 + t3 + t4;
    }
}
__global__ void dkl_final_kernel(const float* __restrict__ part, float* __restrict__ out) {
    float s = 0.0f;
    for (int b = 0; b < BDIM; b++) s += part[b];
    out[0] = s / (float)BDIM;
}

// ---------------- host ----------------
extern "C" void kernel_launch(void* const* d_in, const int* in_sizes, int n_in,
                              void* d_out, int out_size) {
    const float* z    = (const float*)d_in[0];
    const float* mm   = (const float*)d_in[1];
    const float* noise = (const float*)d_in[2];
    const float* Wih0 = (const float*)d_in[3];
    const float* Whh0 = (const float*)d_in[4];
    const float* b0   = (const float*)d_in[5];
    const float* Wih1 = (const float*)d_in[6];
    const float* Whh1 = (const float*)d_in[7];
    const float* b1   = (const float*)d_in[8];

    float* out = (float*)d_out;
    float* mean = out;
    float* cov = out + MEAN_N;
    float* dkl = out + MEAN_N + COV_N;

    float *Pa, *Pb, *Mm, *xin0, *xin1, *zl, *hseq, *gates, *hst, *cst;
    float *wv, *wU, *cv, *Dc, *part;
    cudaGetSymbolAddress((void**)&Pa, g_Pa);
    cudaGetSymbolAddress((void**)&Pb, g_Pb);
    cudaGetSymbolAddress((void**)&Mm, g_Mm);
    cudaGetSymbolAddress((void**)&xin0, g_xin0);
    cudaGetSymbolAddress((void**)&xin1, g_xin1);
    cudaGetSymbolAddress((void**)&zl, g_zl);
    cudaGetSymbolAddress((void**)&hseq, g_hseq);
    cudaGetSymbolAddress((void**)&gates, g_gates);
    cudaGetSymbolAddress((void**)&hst, g_hst);
    cudaGetSymbolAddress((void**)&cst, g_cst);
    cudaGetSymbolAddress((void**)&wv, g_w);
    cudaGetSymbolAddress((void**)&wU, g_wU);
    cudaGetSymbolAddress((void**)&cv, g_cv);
    cudaGetSymbolAddress((void**)&Dc, g_Dc);
    cudaGetSymbolAddress((void**)&part, g_part);

    // init posterior
    init_mean_kernel<<<(int)((MEAN_N + 255) / 256), 256>>>(mean, mm);
    init_cov_kernel<<<(int)((COV_N + 255) / 256), 256>>>(cov);

    // ---- ordering BiLSTM ----
    int nxe = BDIM * EDIM * CDIM;
    build_xin0_kernel<<<(nxe + 255) / 256, 256>>>(xin0, z);
    for (int layer = 0; layer < 2; layer++) {
        const float* xin = layer ? xin1 : xin0;
        const float* Wih = layer ? Wih1 : Wih0;
        const float* Whh = layer ? Whh1 : Whh0;
        const float* bb  = layer ? b1 : b0;
        int nhc = 2 * BDIM * HDIM;
        zero_kernel<<<(nhc + 255) / 256, 256>>>(hst, nhc);
        zero_kernel<<<(nhc + 255) / 256, 256>>>(cst, nhc);
        int nwarp = 2 * BDIM * GDIM;            // 28672 warps
        int gblocks = (nwarp * 32 + 255) / 256;  // 3584
        for (int s = 0; s < EDIM; s++) {
            lstm_gates_kernel<<<gblocks, 256>>>(xin, hst, Wih, Whh, bb, gates, s);
            lstm_update_kernel<<<(nhc + 255) / 256, 256>>>(gates, hst, cst, hseq, s);
        }
        if (layer == 0)
            concat_kernel<<<(nxe + 255) / 256, 256>>>(hseq, xin1);
        else
            build_zl_kernel<<<(nxe + 255) / 256, 256>>>(hseq, zl);
    }

    // ---- episodes ----
    long sP = (long)CDIM * KDIM;   // P batch stride
    long sA = (long)KDIM * CDIM;   // mean batch stride
    long sM = (long)CDIM * CDIM;   // M batch stride
    dim3 g1(CDIM / 64, CDIM / 128, BDIM);  // (14,7,8)  M = P@A
    dim3 g2(KDIM / 64, CDIM / 128, BDIM);  // (8,7,8)   P' = 2P - M@P
    dim3 tg(KDIM / 32, CDIM / 32, BDIM);   // (16,28,8)

    for (int t = 0; t < EDIM; t++) {
        transpose_scale_kernel<<<tg, dim3(32, 8)>>>(mean, Pa);
        // NS step 1: Pa -> Pb
        sgemm_kernel<0><<<g1, 128>>>(Pa, mean, nullptr, Mm, CDIM, CDIM, KDIM, sP, sA, sM);
        sgemm_kernel<1><<<g2, 128>>>(Mm, Pa, Pa, Pb, CDIM, KDIM, CDIM, sM, sP, sP);
        // NS step 2: Pb -> Pa
        sgemm_kernel<0><<<g1, 128>>>(Pb, mean, nullptr, Mm, CDIM, CDIM, KDIM, sP, sA, sM);
        sgemm_kernel<1><<<g2, 128>>>(Mm, Pb, Pb, Pa, CDIM, KDIM, CDIM, sM, sP, sP);
        // NS step 3: Pa -> Pb  (final P in Pb)
        sgemm_kernel<0><<<g1, 128>>>(Pa, mean, nullptr, Mm, CDIM, CDIM, KDIM, sP, sA, sM);
        sgemm_kernel<1><<<g2, 128>>>(Mm, Pa, Pa, Pb, CDIM, KDIM, CDIM, sM, sP, sP);

        w_kernel<<<BDIM, KDIM>>>(zl, noise, Pb, wv, t);
        delta_kernel<<<dim3(CDIM / 128, BDIM), 128>>>(wv, mean, zl, Dc, t);
        wU_kernel<<<dim3(KDIM / 128, BDIM), 128>>>(wv, cov, wU);
        sigma_c_kernel<<<BDIM, KDIM>>>(wv, wU, cv);
        mean_update_kernel<<<(int)((MEAN_N + 255) / 256), 256>>>(mean, cv, Dc);
        cov_update_kernel<<<(int)((COV_N + 255) / 256), 256>>>(cov, cv, wU);
    }

    // ---- KL ----
    dkl_part_kernel<<<BDIM, 256>>>(mean, cov, mm, part);
    dkl_final_kernel<<<1, 1>>>(part, dkl);
    (void)in_sizes; (void)n_in; (void)out_size;
}

// round 3
// speedup vs baseline: 1.5235x; 1.5235x over previous
#include <cuda_runtime.h>
#include <math.h>

#define KDIM 512
#define CDIM 896
#define HDIM 448
#define GDIM 1792   // 4*H
#define BDIM 8
#define EDIM 4
#define ALPHA_F 5e-4f
#define EPS_F 1e-6f
#define OBS_STD_F 0.1f

static const long MEAN_N = (long)BDIM * KDIM * CDIM;   // 3670016
static const long COV_N  = (long)BDIM * KDIM * KDIM;   // 2097152

// ---------------- scratch (no allocations allowed) ----------------
__device__ float g_Pa[BDIM * CDIM * KDIM];
__device__ float g_Pb[BDIM * CDIM * KDIM];
__device__ float g_Mm[BDIM * KDIM * KDIM];   // K x K now (A@P)
__device__ float g_xin0[BDIM * EDIM * CDIM];
__device__ float g_xin1[BDIM * EDIM * CDIM];
__device__ float g_zl[EDIM * BDIM * CDIM];
__device__ float g_hseq[2 * BDIM * EDIM * HDIM];
__device__ float g_gates[2 * BDIM * GDIM];
__device__ float g_hst[2 * BDIM * HDIM];
__device__ float g_cst[2 * BDIM * HDIM];
__device__ float g_w[BDIM * KDIM];
__device__ float g_wU[BDIM * KDIM];
__device__ float g_cv[BDIM * KDIM];
__device__ float g_Dc[BDIM * CDIM];
__device__ float g_part[BDIM];

__device__ __forceinline__ float sigf(float x) { return 1.0f / (1.0f + expf(-x)); }
__device__ __forceinline__ float clipf(float x, float lo, float hi) {
    return fminf(fmaxf(x, lo), hi);
}

// packed fp32x2 FMA (SASS FFMA2; only reachable via explicit PTX)
#define FMA2(accv, av, bv) \
    asm("fma.rn.f32x2 %0, %1, %2, %0;" : "+l"(accv) : "l"(av), "l"(bv))
#define PACK_DUP(dst, a) \
    asm("mov.b64 %0, {%1, %1};" : "=l"(dst) : "f"(a))

// ---------------- init ----------------
__global__ void init_mean_kernel(float* mean, const float* mm) {
    long i = (long)blockIdx.x * blockDim.x + threadIdx.x;
    if (i < MEAN_N) mean[i] = mm[i % ((long)KDIM * CDIM)];
}
__global__ void init_cov_kernel(float* cov) {
    long i = (long)blockIdx.x * blockDim.x + threadIdx.x;
    if (i < COV_N) {
        int j = (int)(i % KDIM);
        int k = (int)((i / KDIM) % KDIM);
        cov[i] = (j == k) ? (1.0f + EPS_F) : 0.0f;
    }
}
__global__ void zero_kernel(float* p, int n) {
    int i = blockIdx.x * blockDim.x + threadIdx.x;
    if (i < n) p[i] = 0.0f;
}

// ---------------- LSTM ----------------
__global__ void build_xin0_kernel(float* xin, const float* z) {
    int i = blockIdx.x * blockDim.x + threadIdx.x;
    int n = BDIM * EDIM * CDIM;
    if (i < n) {
        int c = i % CDIM;
        int t = (i / CDIM) % EDIM;
        int b = i / (CDIM * EDIM);
        xin[i] = z[((long)t * BDIM + b) * CDIM + c];
    }
}

__global__ void lstm_gates_kernel(const float* __restrict__ xin,
                                  const float* __restrict__ hcur,
                                  const float* __restrict__ Wih,
                                  const float* __restrict__ Whh,
                                  const float* __restrict__ bias,
                                  float* __restrict__ gates, int step) {
    int w = (blockIdx.x * blockDim.x + threadIdx.x) >> 5;
    int lane = threadIdx.x & 31;
    if (w >= 2 * BDIM * GDIM) return;
    int j = w % GDIM;
    int b = (w / GDIM) % BDIM;
    int d = w / (GDIM * BDIM);
    int t = (d == 0) ? step : (EDIM - 1 - step);

    const float* x  = xin + ((long)b * EDIM + t) * CDIM;
    const float* wi = Wih + ((long)d * GDIM + j) * CDIM;
    float acc = 0.0f;
#pragma unroll
    for (int c = lane * 4; c < CDIM; c += 128) {
        float4 xv = *(const float4*)(x + c);
        float4 wv = *(const float4*)(wi + c);
        acc += xv.x * wv.x + xv.y * wv.y + xv.z * wv.z + xv.w * wv.w;
    }
    const float* h  = hcur + ((long)d * BDIM + b) * HDIM;
    const float* wh = Whh + ((long)d * GDIM + j) * HDIM;
    for (int c = lane * 4; c < HDIM; c += 128) {
        float4 hv = *(const float4*)(h + c);
        float4 wv = *(const float4*)(wh + c);
        acc += hv.x * wv.x + hv.y * wv.y + hv.z * wv.z + hv.w * wv.w;
    }
#pragma unroll
    for (int o = 16; o > 0; o >>= 1) acc += __shfl_xor_sync(0xffffffffu, acc, o);
    if (lane == 0) gates[((long)d * BDIM + b) * GDIM + j] = acc + bias[(long)d * GDIM + j];
}

__global__ void lstm_update_kernel(const float* __restrict__ gates,
                                   float* __restrict__ hcur, float* __restrict__ ccur,
                                   float* __restrict__ hseq, int step) {
    int i = blockIdx.x * blockDim.x + threadIdx.x;
    int n = 2 * BDIM * HDIM;
    if (i >= n) return;
    int h = i % HDIM;
    int b = (i / HDIM) % BDIM;
    int d = i / (HDIM * BDIM);
    int t = (d == 0) ? step : (EDIM - 1 - step);
    const float* g = gates + ((long)d * BDIM + b) * GDIM;
    float gi = g[h], gf = g[HDIM + h], gg = g[2 * HDIM + h], go = g[3 * HDIM + h];
    float c = ccur[i];
    c = sigf(gf) * c + sigf(gi) * tanhf(gg);
    float hh = sigf(go) * tanhf(c);
    ccur[i] = c;
    hcur[i] = hh;
    hseq[(((long)d * BDIM + b) * EDIM + t) * HDIM + h] = hh;
}

__global__ void concat_kernel(const float* __restrict__ hseq, float* __restrict__ xout) {
    int i = blockIdx.x * blockDim.x + threadIdx.x;
    int n = BDIM * EDIM * CDIM;
    if (i >= n) return;
    int c = i % CDIM;
    int t = (i / CDIM) % EDIM;
    int b = i / (CDIM * EDIM);
    int d = (c >= HDIM) ? 1 : 0;
    int hh = c - d * HDIM;
    xout[i] = hseq[(((long)d * BDIM + b) * EDIM + t) * HDIM + hh];
}
__global__ void build_zl_kernel(const float* __restrict__ hseq, float* __restrict__ zl) {
    int i = blockIdx.x * blockDim.x + threadIdx.x;
    int n = EDIM * BDIM * CDIM;
    if (i >= n) return;
    int c = i % CDIM;
    int b = (i / CDIM) % BDIM;
    int t = i / (CDIM * BDIM);
    int d = (c >= HDIM) ? 1 : 0;
    int hh = c - d * HDIM;
    zl[i] = hseq[(((long)d * BDIM + b) * EDIM + t) * HDIM + hh];
}

// ---------------- transpose-scale: P = alpha * mean^T ----------------
__global__ void transpose_scale_kernel(const float* __restrict__ mean, float* __restrict__ P) {
    __shared__ float tile[32][33];
    int b = blockIdx.z;
    int k0 = blockIdx.x * 32, c0 = blockIdx.y * 32;
    const float* M = mean + (long)b * KDIM * CDIM;
    float* Pp = P + (long)b * CDIM * KDIM;
    for (int i = threadIdx.y; i < 32; i += 8)
        tile[i][threadIdx.x] = M[(long)(k0 + i) * CDIM + c0 + threadIdx.x];
    __syncthreads();
    for (int i = threadIdx.y; i < 32; i += 8)
        Pp[(long)(c0 + i) * KDIM + k0 + threadIdx.x] = ALPHA_F * tile[threadIdx.x][i];
}

// ---------------- batched SGEMM 128x64x8, 128 threads, FFMA2 inner ----------------
// C = A(MxKd, ld=Kd) @ B(KdxN, ld=N); EPI: C = 2*Ead - A@B
template <int EPI>
__global__ __launch_bounds__(128) void sgemm_kernel(
    const float* __restrict__ A, const float* __restrict__ B,
    const float* __restrict__ Ead, float* __restrict__ C,
    int Ndim, int Kd, long sA, long sB, long sC) {
    int bb = blockIdx.z;
    A += (long)bb * sA;
    B += (long)bb * sB;
    C += (long)bb * sC;
    if (EPI) Ead += (long)bb * sC;

    int m0 = blockIdx.y * 128, n0 = blockIdx.x * 64;
    __shared__ float As[8][128];
    __shared__ float Bs[8][64];
    int tid = threadIdx.x;
    int ty = tid >> 3, tx = tid & 7;   // 16 x 8
    unsigned long long acc2[8][4];
#pragma unroll
    for (int i = 0; i < 8; i++)
#pragma unroll
        for (int j = 0; j < 4; j++) acc2[i][j] = 0ULL;

    const float* Ag = A + (long)(m0 + tid) * Kd;
    int brow = tid >> 4, bcol = (tid & 15) * 4;
    const float* Bg = B + (long)brow * Ndim + n0 + bcol;

    for (int k0 = 0; k0 < Kd; k0 += 8) {
        float4 a0 = *(const float4*)(Ag + k0);
        float4 a1 = *(const float4*)(Ag + k0 + 4);
        float4 b0 = *(const float4*)(Bg + (long)k0 * Ndim);
        As[0][tid] = a0.x; As[1][tid] = a0.y; As[2][tid] = a0.z; As[3][tid] = a0.w;
        As[4][tid] = a1.x; As[5][tid] = a1.y; As[6][tid] = a1.z; As[7][tid] = a1.w;
        *(float4*)&Bs[brow][bcol] = b0;
        __syncthreads();
#pragma unroll
        for (int kk = 0; kk < 8; kk++) {
            float ar[8];
            *(float4*)ar = *(float4*)&As[kk][ty * 8];
            *(float4*)(ar + 4) = *(float4*)&As[kk][ty * 8 + 4];
            unsigned long long br2[4];
            const unsigned long long* bp = (const unsigned long long*)&Bs[kk][tx * 8];
            br2[0] = bp[0]; br2[1] = bp[1]; br2[2] = bp[2]; br2[3] = bp[3];
#pragma unroll
            for (int i = 0; i < 8; i++) {
                unsigned long long a2;
                PACK_DUP(a2, ar[i]);
#pragma unroll
                for (int j = 0; j < 4; j++) FMA2(acc2[i][j], a2, br2[j]);
            }
        }
        __syncthreads();
    }
#pragma unroll
    for (int i = 0; i < 8; i++) {
        long row = m0 + ty * 8 + i;
        float* Cr = C + row * Ndim + n0 + tx * 8;
        float accf[8];
#pragma unroll
        for (int j = 0; j < 4; j++) *(float2*)(accf + 2 * j) = *(float2*)&acc2[i][j];
        if (EPI) {
            const float* Er = Ead + row * Ndim + n0 + tx * 8;
#pragma unroll
            for (int j = 0; j < 8; j += 4) {
                float4 e = *(const float4*)(Er + j);
                float4 v;
                v.x = 2.0f * e.x - accf[j];
                v.y = 2.0f * e.y - accf[j + 1];
                v.z = 2.0f * e.z - accf[j + 2];
                v.w = 2.0f * e.w - accf[j + 3];
                *(float4*)(Cr + j) = v;
            }
        } else {
#pragma unroll
            for (int j = 0; j < 8; j += 4) {
                float4 v;
                v.x = accf[j]; v.y = accf[j + 1]; v.z = accf[j + 2]; v.w = accf[j + 3];
                *(float4*)(Cr + j) = v;
            }
        }
    }
}

// ---------------- episode update kernels ----------------
__global__ void w_kernel(const float* __restrict__ zl, const float* __restrict__ noise,
                         const float* __restrict__ P, float* __restrict__ wv, int t) {
    int b = blockIdx.x;
    int k = threadIdx.x;  // 512
    __shared__ float zn[CDIM];
    const float* zr = zl + ((long)t * BDIM + b) * CDIM;
    const float* nr = noise + ((long)t * BDIM + b) * CDIM;
    for (int c = k; c < CDIM; c += KDIM) zn[c] = zr[c] + OBS_STD_F * nr[c];
    __syncthreads();
    const float* Pb = P + (long)b * CDIM * KDIM;
    float acc = 0.0f;
    for (int c = 0; c < CDIM; c++) acc += zn[c] * Pb[(long)c * KDIM + k];
    wv[b * KDIM + k] = acc;
}

__global__ void delta_kernel(const float* __restrict__ wv, const float* __restrict__ mean,
                             const float* __restrict__ zl, float* __restrict__ Dc, int t) {
    int b = blockIdx.y;
    int c = blockIdx.x * 128 + threadIdx.x;
    __shared__ float sw[KDIM];
    for (int k = threadIdx.x; k < KDIM; k += 128) sw[k] = wv[b * KDIM + k];
    __syncthreads();
    const float* M = mean + (long)b * KDIM * CDIM;
    float acc = 0.0f;
    for (int k = 0; k < KDIM; k++) acc += sw[k] * M[(long)k * CDIM + c];
    float d = zl[((long)t * BDIM + b) * CDIM + c] - acc;
    Dc[b * CDIM + c] = clipf(d, -100.0f, 100.0f);
}

__global__ void wU_kernel(const float* __restrict__ wv, const float* __restrict__ cov,
                          float* __restrict__ wU) {
    int b = blockIdx.y;
    int j = blockIdx.x * 128 + threadIdx.x;
    __shared__ float sw[KDIM];
    for (int k = threadIdx.x; k < KDIM; k += 128) sw[k] = wv[b * KDIM + k];
    __syncthreads();
    const float* Cb = cov + (long)b * KDIM * KDIM;
    float acc = 0.0f;
    for (int k = 0; k < KDIM; k++) acc += sw[k] * Cb[(long)k * KDIM + j];
    wU[b * KDIM + j] = acc;
}

__global__ void sigma_c_kernel(const float* __restrict__ wv, const float* __restrict__ wU,
                               float* __restrict__ cv) {
    int b = blockIdx.x;
    int k = threadIdx.x;  // 512
    __shared__ float red[KDIM];
    float u = wU[b * KDIM + k];
    red[k] = u * wv[b * KDIM + k];
    __syncthreads();
    for (int s = 256; s > 0; s >>= 1) {
        if (k < s) red[k] += red[k + s];
        __syncthreads();
    }
    float sigma = fmaxf(red[0] + OBS_STD_F * OBS_STD_F, EPS_F);
    cv[b * KDIM + k] = clipf(u / sigma, -1000.0f, 1000.0f);
}

__global__ void mean_update_kernel(float* __restrict__ mean, const float* __restrict__ cv,
                                   const float* __restrict__ Dc) {
    long i = (long)blockIdx.x * blockDim.x + threadIdx.x;
    if (i >= MEAN_N) return;
    int c = (int)(i % CDIM);
    int k = (int)((i / CDIM) % KDIM);
    int b = (int)(i / ((long)CDIM * KDIM));
    float v = mean[i] + cv[b * KDIM + k] * Dc[b * CDIM + c];
    mean[i] = clipf(v, -1000.0f, 1000.0f);
}

__global__ void cov_update_kernel(float* __restrict__ cov, const float* __restrict__ cv,
                                  const float* __restrict__ wU) {
    long i = (long)blockIdx.x * blockDim.x + threadIdx.x;
    if (i >= COV_N) return;
    int j = (int)(i % KDIM);
    int k = (int)((i / KDIM) % KDIM);
    int b = (int)(i / ((long)KDIM * KDIM));
    float ci = cv[b * KDIM + k], cj = cv[b * KDIM + j];
    float ui = wU[b * KDIM + k], uj = wU[b * KDIM + j];
    float old = cov[i];
    float v;
    if (k == j) {
        v = clipf(old - ci * ui, 0.001f, 1000.0f) + EPS_F;
    } else {
        v = old - 0.5f * (ci * uj + cj * ui);
    }
    cov[i] = v;
}

// ---------------- KL ----------------
__global__ void dkl_part_kernel(const float* __restrict__ mean, const float* __restrict__ cov,
                                const float* __restrict__ prior, float* __restrict__ part) {
    int b = blockIdx.x;
    int tid = threadIdx.x;  // 256
    const float pdiag = 1.0f + EPS_F;
    float rsum = 0.0f, lsum = 0.0f;
    const float* Cb = cov + (long)b * KDIM * KDIM;
    for (int k = tid; k < KDIM; k += 256) {
        float q = clipf(Cb[(long)k * KDIM + k], 0.001f, 1e6f);
        rsum += clipf(q / pdiag, EPS_F, 1000.0f);
        lsum += clipf(logf(pdiag) - logf(q), -10.0f, 10.0f);
    }
    float t2a = 0.0f, t2b = 0.0f;
    const float* Mb = mean + (long)b * KDIM * CDIM;
    long n = (long)KDIM * CDIM;
    for (long i = tid; i < n; i += 512) {
        float d = Mb[i] - prior[i];
        t2a += fminf(d * d, 1000.0f);
        long i2 = i + 256;
        if (i2 < n) {
            float d2 = Mb[i2] - prior[i2];
            t2b += fminf(d2 * d2, 1000.0f);
        }
    }
    float t2s = t2a + t2b;
    __shared__ double sd[256];
    sd[tid] = (double)rsum;
    __syncthreads();
    for (int s = 128; s > 0; s >>= 1) { if (tid < s) sd[tid] += sd[tid + s]; __syncthreads(); }
    double Rs = sd[0]; __syncthreads();
    sd[tid] = (double)lsum;
    __syncthreads();
    for (int s = 128; s > 0; s >>= 1) { if (tid < s) sd[tid] += sd[tid + s]; __syncthreads(); }
    double Ls = sd[0]; __syncthreads();
    sd[tid] = (double)t2s;
    __syncthreads();
    for (int s = 128; s > 0; s >>= 1) { if (tid < s) sd[tid] += sd[tid + s]; __syncthreads(); }
    double T2s = sd[0];
    if (tid == 0) {
        float t1 = clipf((float)CDIM * (float)Rs, -1e6f, 1e6f);
        float t2 = clipf((float)(T2s) / pdiag, -1e6f, 1e6f);
        float t3 = -(float)CDIM * (float)KDIM;
        float t4 = clipf((float)CDIM * (float)Ls, -1e6f, 1e6f);
        part[b] = t1 + t2 + t3 + t4;
    }
}
__global__ void dkl_final_kernel(const float* __restrict__ part, float* __restrict__ out) {
    float s = 0.0f;
    for (int b = 0; b < BDIM; b++) s += part[b];
    out[0] = s / (float)BDIM;
}

// ---------------- host ----------------
extern "C" void kernel_launch(void* const* d_in, const int* in_sizes, int n_in,
                              void* d_out, int out_size) {
    const float* z    = (const float*)d_in[0];
    const float* mm   = (const float*)d_in[1];
    const float* noise = (const float*)d_in[2];
    const float* Wih0 = (const float*)d_in[3];
    const float* Whh0 = (const float*)d_in[4];
    const float* b0   = (const float*)d_in[5];
    const float* Wih1 = (const float*)d_in[6];
    const float* Whh1 = (const float*)d_in[7];
    const float* b1   = (const float*)d_in[8];

    float* out = (float*)d_out;
    float* mean = out;
    float* cov = out + MEAN_N;
    float* dkl = out + MEAN_N + COV_N;

    float *Pa, *Pb, *Mm, *xin0, *xin1, *zl, *hseq, *gates, *hst, *cst;
    float *wv, *wU, *cv, *Dc, *part;
    cudaGetSymbolAddress((void**)&Pa, g_Pa);
    cudaGetSymbolAddress((void**)&Pb, g_Pb);
    cudaGetSymbolAddress((void**)&Mm, g_Mm);
    cudaGetSymbolAddress((void**)&xin0, g_xin0);
    cudaGetSymbolAddress((void**)&xin1, g_xin1);
    cudaGetSymbolAddress((void**)&zl, g_zl);
    cudaGetSymbolAddress((void**)&hseq, g_hseq);
    cudaGetSymbolAddress((void**)&gates, g_gates);
    cudaGetSymbolAddress((void**)&hst, g_hst);
    cudaGetSymbolAddress((void**)&cst, g_cst);
    cudaGetSymbolAddress((void**)&wv, g_w);
    cudaGetSymbolAddress((void**)&wU, g_wU);
    cudaGetSymbolAddress((void**)&cv, g_cv);
    cudaGetSymbolAddress((void**)&Dc, g_Dc);
    cudaGetSymbolAddress((void**)&part, g_part);

    init_mean_kernel<<<(int)((MEAN_N + 255) / 256), 256>>>(mean, mm);
    init_cov_kernel<<<(int)((COV_N + 255) / 256), 256>>>(cov);

    // ---- ordering BiLSTM ----
    int nxe = BDIM * EDIM * CDIM;
    build_xin0_kernel<<<(nxe + 255) / 256, 256>>>(xin0, z);
    for (int layer = 0; layer < 2; layer++) {
        const float* xin = layer ? xin1 : xin0;
        const float* Wih = layer ? Wih1 : Wih0;
        const float* Whh = layer ? Whh1 : Whh0;
        const float* bb  = layer ? b1 : b0;
        int nhc = 2 * BDIM * HDIM;
        zero_kernel<<<(nhc + 255) / 256, 256>>>(hst, nhc);
        zero_kernel<<<(nhc + 255) / 256, 256>>>(cst, nhc);
        int nwarp = 2 * BDIM * GDIM;
        int gblocks = (nwarp * 32 + 255) / 256;
        for (int s = 0; s < EDIM; s++) {
            lstm_gates_kernel<<<gblocks, 256>>>(xin, hst, Wih, Whh, bb, gates, s);
            lstm_update_kernel<<<(nhc + 255) / 256, 256>>>(gates, hst, cst, hseq, s);
        }
        if (layer == 0)
            concat_kernel<<<(nxe + 255) / 256, 256>>>(hseq, xin1);
        else
            build_zl_kernel<<<(nxe + 255) / 256, 256>>>(hseq, zl);
    }

    // ---- episodes ----
    // NS re-associated: Mk = A@P (KxK), P' = 2P - P@Mk
    long sP = (long)CDIM * KDIM;
    long sA = (long)KDIM * CDIM;
    long sM = (long)KDIM * KDIM;
    dim3 g1(KDIM / 64, KDIM / 128, BDIM);  // (8,4,8)  Mk = mean @ P : 512x512x896
    dim3 g2(KDIM / 64, CDIM / 128, BDIM);  // (8,7,8)  P' = 2P - P@Mk : 896x512x512
    dim3 tg(KDIM / 32, CDIM / 32, BDIM);

    for (int t = 0; t < EDIM; t++) {
        transpose_scale_kernel<<<tg, dim3(32, 8)>>>(mean, Pa);
        // NS step 1: Pa -> Pb
        sgemm_kernel<0><<<g1, 128>>>(mean, Pa, nullptr, Mm, KDIM, CDIM, sA, sP, sM);
        sgemm_kernel<1><<<g2, 128>>>(Pa, Mm, Pa, Pb, KDIM, KDIM, sP, sM, sP);
        // NS step 2: Pb -> Pa
        sgemm_kernel<0><<<g1, 128>>>(mean, Pb, nullptr, Mm, KDIM, CDIM, sA, sP, sM);
        sgemm_kernel<1><<<g2, 128>>>(Pb, Mm, Pb, Pa, KDIM, KDIM, sP, sM, sP);
        // NS step 3: Pa -> Pb  (final P in Pb)
        sgemm_kernel<0><<<g1, 128>>>(mean, Pa, nullptr, Mm, KDIM, CDIM, sA, sP, sM);
        sgemm_kernel<1><<<g2, 128>>>(Pa, Mm, Pa, Pb, KDIM, KDIM, sP, sM, sP);

        w_kernel<<<BDIM, KDIM>>>(zl, noise, Pb, wv, t);
        delta_kernel<<<dim3(CDIM / 128, BDIM), 128>>>(wv, mean, zl, Dc, t);
        wU_kernel<<<dim3(KDIM / 128, BDIM), 128>>>(wv, cov, wU);
        sigma_c_kernel<<<BDIM, KDIM>>>(wv, wU, cv);
        mean_update_kernel<<<(int)((MEAN_N + 255) / 256), 256>>>(mean, cv, Dc);
        cov_update_kernel<<<(int)((COV_N + 255) / 256), 256>>>(cov, cv, wU);
    }

    // ---- KL ----
    dkl_part_kernel<<<BDIM, 256>>>(mean, cov, mm, part);
    dkl_final_kernel<<<1, 1>>>(part, dkl);
    (void)in_sizes; (void)n_in; (void)out_size;
}